// round 5
// baseline (speedup 1.0000x reference)
#include <cuda_runtime.h>
#include <math.h>

#define NN 50000
#define NE 800000
#define DD 128
#define ED 16
#define SCAN_NBLK ((NN + 1023) / 1024)   // 49

typedef unsigned long long ull;

// Scratch (allocation-free rule: __device__ globals)
__device__ float g_bufA[NN * DD];
__device__ float g_bufB[NN * DD];
__device__ int   g_idx64;
__device__ int   g_cnt[NN];
__device__ int   g_rowptr[NN + 1];
__device__ int   g_cursor[NN];
__device__ int   g_blocksum[SCAN_NBLK];
__device__ int   g_blockoff[SCAN_NBLK];
__device__ int   g_src[NE];              // src node, dst-sorted
__device__ int   g_eid[NE];              // original edge id, dst-sorted
__device__ float g_eattr[NE * ED];       // edge_attr rows in dst-sorted order

// ---------------------------------------------------------------------------
// f32x2 packed-FMA helpers (Blackwell FFMA2 — bit-identical fp32 per lane)
// ---------------------------------------------------------------------------
__device__ __forceinline__ ull packdup(float a) {
    ull r; unsigned int u = __float_as_uint(a);
    asm("mov.b64 %0, {%1, %2};" : "=l"(r) : "r"(u), "r"(u));
    return r;
}
__device__ __forceinline__ void fma2(ull& d, ull a, ull b) {
    asm("fma.rn.f32x2 %0, %1, %2, %3;" : "=l"(d) : "l"(a), "l"(b), "l"(d));
}
__device__ __forceinline__ float2 unpack2(ull v) {
    unsigned int lo, hi;
    asm("mov.b64 {%0, %1}, %2;" : "=r"(lo), "=r"(hi) : "l"(v));
    return make_float2(__uint_as_float(lo), __uint_as_float(hi));
}

// ---------------------------------------------------------------------------
// Detect int64 vs int32 edge_idx (one warp, ballot)
// ---------------------------------------------------------------------------
__global__ void detect_idx_kernel(const long long* __restrict__ idx) {
    int lane = threadIdx.x;
    long long v = idx[lane];
    int bad = (v < 0 || v >= (long long)NN) ? 1 : 0;
    unsigned m = __ballot_sync(0xffffffffu, bad);
    if (lane == 0) g_idx64 = (m == 0u);
}

// ---------------------------------------------------------------------------
// CSR build
// ---------------------------------------------------------------------------
__global__ void zero_cnt_kernel() {
    int i = blockIdx.x * blockDim.x + threadIdx.x;
    if (i < NN) g_cnt[i] = 0;
}

__global__ void hist_kernel(const void* __restrict__ edge_idx) {
    int e = blockIdx.x * blockDim.x + threadIdx.x;
    if (e >= NE) return;
    int dst;
    if (g_idx64) dst = (int)((const long long*)edge_idx)[NE + e];
    else         dst = ((const int*)edge_idx)[NE + e];
    atomicAdd(&g_cnt[dst], 1);
}

__global__ void local_scan_kernel() {
    __shared__ int sdata[1024];
    int i = blockIdx.x * 1024 + threadIdx.x;
    int v = (i < NN) ? g_cnt[i] : 0;
    sdata[threadIdx.x] = v;
    __syncthreads();
    #pragma unroll
    for (int off = 1; off < 1024; off <<= 1) {
        int t = (threadIdx.x >= off) ? sdata[threadIdx.x - off] : 0;
        __syncthreads();
        sdata[threadIdx.x] += t;
        __syncthreads();
    }
    if (i < NN) g_rowptr[i] = sdata[threadIdx.x] - v;   // local exclusive
    if (threadIdx.x == 1023) g_blocksum[blockIdx.x] = sdata[1023];
}

__global__ void scan_sums_kernel() {
    __shared__ int sd[64];
    int t = threadIdx.x;
    int v = (t < SCAN_NBLK) ? g_blocksum[t] : 0;
    sd[t] = v;
    __syncthreads();
    #pragma unroll
    for (int off = 1; off < 64; off <<= 1) {
        int u = (t >= off) ? sd[t - off] : 0;
        __syncthreads();
        sd[t] += u;
        __syncthreads();
    }
    if (t < SCAN_NBLK) g_blockoff[t] = sd[t] - v;   // exclusive
}

__global__ void add_off_kernel() {
    int i = blockIdx.x * 1024 + threadIdx.x;
    if (i < NN) {
        int v = g_rowptr[i] + g_blockoff[blockIdx.x];
        g_rowptr[i] = v;
        g_cursor[i] = v;
    }
    if (i == 0) g_rowptr[NN] = NE;
}

__global__ void scatter_kernel(const void* __restrict__ edge_idx) {
    int e = blockIdx.x * blockDim.x + threadIdx.x;
    if (e >= NE) return;
    int src, dst;
    if (g_idx64) {
        src = (int)((const long long*)edge_idx)[e];
        dst = (int)((const long long*)edge_idx)[NE + e];
    } else {
        src = ((const int*)edge_idx)[e];
        dst = ((const int*)edge_idx)[NE + e];
    }
    int pos = atomicAdd(&g_cursor[dst], 1);
    g_src[pos] = src;
    g_eid[pos] = e;
}

// Gather edge_attr rows into dst-sorted order (coalesced writes).
__global__ void gather_attr_kernel(const float* __restrict__ edge_attr) {
    int i = blockIdx.x * blockDim.x + threadIdx.x;   // one float4 per thread
    if (i >= NE * 4) return;
    int j = i >> 2, c = i & 3;
    int eid = g_eid[j];
    ((float4*)g_eattr)[(size_t)j * 4 + c] =
        ((const float4*)edge_attr)[(size_t)eid * 4 + c];
}

// ---------------------------------------------------------------------------
// Edge aggregation (CSR, no atomics): one warp per dst node, FFMA2 chains.
// ---------------------------------------------------------------------------
#define MCHAIN2(mA, mB, t0, t1, t2, t3)          \
    { ull d;                                      \
      d = packdup(t0.x); fma2(mA, d, wA[0]);  fma2(mB, d, wB[0]);   \
      d = packdup(t0.y); fma2(mA, d, wA[1]);  fma2(mB, d, wB[1]);   \
      d = packdup(t0.z); fma2(mA, d, wA[2]);  fma2(mB, d, wB[2]);   \
      d = packdup(t0.w); fma2(mA, d, wA[3]);  fma2(mB, d, wB[3]);   \
      d = packdup(t1.x); fma2(mA, d, wA[4]);  fma2(mB, d, wB[4]);   \
      d = packdup(t1.y); fma2(mA, d, wA[5]);  fma2(mB, d, wB[5]);   \
      d = packdup(t1.z); fma2(mA, d, wA[6]);  fma2(mB, d, wB[6]);   \
      d = packdup(t1.w); fma2(mA, d, wA[7]);  fma2(mB, d, wB[7]);   \
      d = packdup(t2.x); fma2(mA, d, wA[8]);  fma2(mB, d, wB[8]);   \
      d = packdup(t2.y); fma2(mA, d, wA[9]);  fma2(mB, d, wB[9]);   \
      d = packdup(t2.z); fma2(mA, d, wA[10]); fma2(mB, d, wB[10]);  \
      d = packdup(t2.w); fma2(mA, d, wA[11]); fma2(mB, d, wB[11]);  \
      d = packdup(t3.x); fma2(mA, d, wA[12]); fma2(mB, d, wB[12]);  \
      d = packdup(t3.y); fma2(mA, d, wA[13]); fma2(mB, d, wB[13]);  \
      d = packdup(t3.z); fma2(mA, d, wA[14]); fma2(mB, d, wB[14]);  \
      d = packdup(t3.w); fma2(mA, d, wA[15]); fma2(mB, d, wB[15]); }

__global__ void __launch_bounds__(256)
aggr_kernel(const float* __restrict__ xin,
            const float* __restrict__ We,
            const float* __restrict__ be,
            const float* __restrict__ eps, int l,
            float* __restrict__ aggr) {
    int lane = threadIdx.x & 31;
    int warp = (blockIdx.x * blockDim.x + threadIdx.x) >> 5;
    int nwarps = (gridDim.x * blockDim.x) >> 5;
    int c0 = lane * 4;

    // We columns for this lane, as native 64-bit pairs: wA=(x,y), wB=(z,w)
    ull wA[ED], wB[ED];
    #pragma unroll
    for (int k = 0; k < ED; k++) {
        double2 wv = *(const double2*)(We + k * DD + c0);
        wA[k] = __double_as_longlong(wv.x);
        wB[k] = __double_as_longlong(wv.y);
    }
    double2 bv = *(const double2*)(be + c0);
    ull biasA = __double_as_longlong(bv.x);
    ull biasB = __double_as_longlong(bv.y);
    float s = 1.0f + eps[l];

    for (int d = warp; d < NN; d += nwarps) {
        float4 xv = *(const float4*)(xin + (size_t)d * DD + c0);
        float4 acc = make_float4(xv.x * s, xv.y * s, xv.z * s, xv.w * s);
        int beg = g_rowptr[d], end = g_rowptr[d + 1];

        int j = beg;
        for (; j + 1 < end; j += 2) {
            int s0 = g_src[j];
            int s1 = g_src[j + 1];
            const float4* p0 = (const float4*)(g_eattr + (size_t)j * ED);
            float4 a0 = p0[0], a1 = p0[1], a2 = p0[2], a3 = p0[3];
            float4 b0 = p0[4], b1 = p0[5], b2 = p0[6], b3 = p0[7];
            float4 xs0 = *(const float4*)(xin + (size_t)s0 * DD + c0);
            float4 xs1 = *(const float4*)(xin + (size_t)s1 * DD + c0);

            ull m0A = biasA, m0B = biasB;
            MCHAIN2(m0A, m0B, a0, a1, a2, a3)
            ull m1A = biasA, m1B = biasB;
            MCHAIN2(m1A, m1B, b0, b1, b2, b3)

            float2 u0A = unpack2(m0A), u0B = unpack2(m0B);
            float2 u1A = unpack2(m1A), u1B = unpack2(m1B);
            acc.x += fmaxf(u0A.x + xs0.x, 0.0f) + fmaxf(u1A.x + xs1.x, 0.0f);
            acc.y += fmaxf(u0A.y + xs0.y, 0.0f) + fmaxf(u1A.y + xs1.y, 0.0f);
            acc.z += fmaxf(u0B.x + xs0.z, 0.0f) + fmaxf(u1B.x + xs1.z, 0.0f);
            acc.w += fmaxf(u0B.y + xs0.w, 0.0f) + fmaxf(u1B.y + xs1.w, 0.0f);
        }
        if (j < end) {
            int s0 = g_src[j];
            const float4* p0 = (const float4*)(g_eattr + (size_t)j * ED);
            float4 a0 = p0[0], a1 = p0[1], a2 = p0[2], a3 = p0[3];
            float4 xs0 = *(const float4*)(xin + (size_t)s0 * DD + c0);
            ull m0A = biasA, m0B = biasB;
            MCHAIN2(m0A, m0B, a0, a1, a2, a3)
            float2 u0A = unpack2(m0A), u0B = unpack2(m0B);
            acc.x += fmaxf(u0A.x + xs0.x, 0.0f);
            acc.y += fmaxf(u0A.y + xs0.y, 0.0f);
            acc.z += fmaxf(u0B.x + xs0.z, 0.0f);
            acc.w += fmaxf(u0B.y + xs0.w, 0.0f);
        }
        *(float4*)(aggr + (size_t)d * DD + c0) = acc;
    }
}

// ---------------------------------------------------------------------------
// Fused node MLP: C = gelu_exact(A @ W1 + b1) @ W2 + b2
// 512 threads, 128-row tiles, 4x8 register tile per thread, FFMA2 inner loop.
// ---------------------------------------------------------------------------
#define SA_PITCH 132
#define MLP_SMEM_FLOATS (128 * SA_PITCH + 2 * 128 * 128 + 256)
#define MLP_SMEM_BYTES (MLP_SMEM_FLOATS * 4)

__global__ void __launch_bounds__(512)
mlp_kernel(const float* __restrict__ A,
           const float* __restrict__ W1g,
           const float* __restrict__ b1g,
           const float* __restrict__ W2g,
           const float* __restrict__ b2g,
           float* __restrict__ C) {
    extern __shared__ float sm[];
    float* sA  = sm;                      // 128 x 132 (padded)
    float* sW1 = sm + 128 * SA_PITCH;     // 128 x 128
    float* sW2 = sW1 + 128 * 128;         // 128 x 128
    float* sb1 = sW2 + 128 * 128;         // 128
    float* sb2 = sb1 + 128;               // 128

    int tid = threadIdx.x;
    int row0 = blockIdx.x * 128;

    for (int i = tid; i < 128 * 32; i += 512) {
        ((float4*)sW1)[i] = ((const float4*)W1g)[i];
        ((float4*)sW2)[i] = ((const float4*)W2g)[i];
    }
    if (tid < 128) { sb1[tid] = b1g[tid]; sb2[tid] = b2g[tid]; }
    for (int i = tid; i < 128 * 32; i += 512) {
        int r = i >> 5, k4 = i & 31;
        int gr = row0 + r;
        float4 v = (gr < NN) ? ((const float4*)(A + (size_t)gr * DD))[k4]
                             : make_float4(0.f, 0.f, 0.f, 0.f);
        *(float4*)(sA + r * SA_PITCH + k4 * 4) = v;
    }
    __syncthreads();

    int tx = tid & 15, ty = tid >> 4;     // 16 col groups, 32 row groups
    int r0 = ty * 4, cc = tx * 8;         // 4 rows x 8 cols (4 col-pairs)

    ull acc[4][4];
    #pragma unroll
    for (int i = 0; i < 4; i++)
        #pragma unroll
        for (int j = 0; j < 4; j++) acc[i][j] = 0ULL;

    // GEMM1: acc = A @ W1 (FFMA2: col-pairs packed)
    #pragma unroll 4
    for (int k = 0; k < 128; k++) {
        double2 w01 = *(const double2*)(sW1 + k * 128 + cc);
        double2 w23 = *(const double2*)(sW1 + k * 128 + cc + 4);
        ull wp0 = __double_as_longlong(w01.x);
        ull wp1 = __double_as_longlong(w01.y);
        ull wp2 = __double_as_longlong(w23.x);
        ull wp3 = __double_as_longlong(w23.y);
        #pragma unroll
        for (int i = 0; i < 4; i++) {
            ull ad = packdup(sA[(r0 + i) * SA_PITCH + k]);
            fma2(acc[i][0], ad, wp0);
            fma2(acc[i][1], ad, wp1);
            fma2(acc[i][2], ad, wp2);
            fma2(acc[i][3], ad, wp3);
        }
    }
    __syncthreads();

    // bias + exact GELU -> sA ; reset acc
    #pragma unroll
    for (int i = 0; i < 4; i++) {
        #pragma unroll
        for (int j = 0; j < 4; j++) {
            float2 u = unpack2(acc[i][j]);
            float h0 = u.x + sb1[cc + 2 * j];
            float h1 = u.y + sb1[cc + 2 * j + 1];
            h0 = 0.5f * h0 * (1.0f + erff(h0 * 0.70710678118654752f));
            h1 = 0.5f * h1 * (1.0f + erff(h1 * 0.70710678118654752f));
            sA[(r0 + i) * SA_PITCH + cc + 2 * j]     = h0;
            sA[(r0 + i) * SA_PITCH + cc + 2 * j + 1] = h1;
            acc[i][j] = 0ULL;
        }
    }
    __syncthreads();

    // GEMM2: acc = H @ W2
    #pragma unroll 4
    for (int k = 0; k < 128; k++) {
        double2 w01 = *(const double2*)(sW2 + k * 128 + cc);
        double2 w23 = *(const double2*)(sW2 + k * 128 + cc + 4);
        ull wp0 = __double_as_longlong(w01.x);
        ull wp1 = __double_as_longlong(w01.y);
        ull wp2 = __double_as_longlong(w23.x);
        ull wp3 = __double_as_longlong(w23.y);
        #pragma unroll
        for (int i = 0; i < 4; i++) {
            ull ad = packdup(sA[(r0 + i) * SA_PITCH + k]);
            fma2(acc[i][0], ad, wp0);
            fma2(acc[i][1], ad, wp1);
            fma2(acc[i][2], ad, wp2);
            fma2(acc[i][3], ad, wp3);
        }
    }

    // bias + store
    #pragma unroll
    for (int i = 0; i < 4; i++) {
        int gr = row0 + r0 + i;
        if (gr < NN) {
            float2 u0 = unpack2(acc[i][0]);
            float2 u1 = unpack2(acc[i][1]);
            float2 u2 = unpack2(acc[i][2]);
            float2 u3 = unpack2(acc[i][3]);
            float4 o0 = make_float4(u0.x + sb2[cc],     u0.y + sb2[cc + 1],
                                    u1.x + sb2[cc + 2], u1.y + sb2[cc + 3]);
            float4 o1 = make_float4(u2.x + sb2[cc + 4], u2.y + sb2[cc + 5],
                                    u3.x + sb2[cc + 6], u3.y + sb2[cc + 7]);
            *(float4*)(C + (size_t)gr * DD + cc) = o0;
            *(float4*)(C + (size_t)gr * DD + cc + 4) = o1;
        }
    }
}

// ---------------------------------------------------------------------------
// Launch
// ---------------------------------------------------------------------------
extern "C" void kernel_launch(void* const* d_in, const int* in_sizes, int n_in,
                              void* d_out, int out_size) {
    const float* x         = (const float*)d_in[0];
    const float* edge_attr = (const float*)d_in[1];
    const float* W1        = (const float*)d_in[2];
    const float* b1        = (const float*)d_in[3];
    const float* W2        = (const float*)d_in[4];
    const float* b2        = (const float*)d_in[5];
    const float* We        = (const float*)d_in[6];
    const float* be        = (const float*)d_in[7];
    const float* eps       = (const float*)d_in[8];
    const void*  edge_idx  = d_in[9];
    float* out = (float*)d_out;

    float *bufA, *bufB;
    cudaGetSymbolAddress((void**)&bufA, g_bufA);
    cudaGetSymbolAddress((void**)&bufB, g_bufB);

    cudaFuncSetAttribute(mlp_kernel,
                         cudaFuncAttributeMaxDynamicSharedMemorySize,
                         MLP_SMEM_BYTES);

    // ---- CSR build + attr pre-sort (once per launch) ----
    detect_idx_kernel<<<1, 32>>>((const long long*)edge_idx);
    zero_cnt_kernel<<<(NN + 255) / 256, 256>>>();
    hist_kernel<<<(NE + 255) / 256, 256>>>(edge_idx);
    local_scan_kernel<<<SCAN_NBLK, 1024>>>();
    scan_sums_kernel<<<1, 64>>>();
    add_off_kernel<<<SCAN_NBLK, 1024>>>();
    scatter_kernel<<<(NE + 255) / 256, 256>>>(edge_idx);
    gather_attr_kernel<<<(NE * 4 + 255) / 256, 256>>>(edge_attr);

    const int aggr_blocks = (NN * 32 + 255) / 256;   // one warp per node
    const int mlp_blocks  = (NN + 127) / 128;

    const float* xin = x;
    for (int l = 0; l < 3; l++) {
        float* aggr = (l == 1) ? bufB : bufA;
        float* xout = (l == 0) ? bufA : ((l == 1) ? bufB : out);

        aggr_kernel<<<aggr_blocks, 256>>>(xin, We + l * ED * DD,
                                          be + l * DD, eps, l, aggr);
        mlp_kernel<<<mlp_blocks, 512, MLP_SMEM_BYTES>>>(
            aggr, W1 + l * DD * DD, b1 + l * DD,
            W2 + l * DD * DD, b2 + l * DD, xout);
        xin = xout;
    }
}

// round 6
// speedup vs baseline: 1.0975x; 1.0975x over previous
#include <cuda_runtime.h>
#include <math.h>

#define NN 50000
#define NE 800000
#define DD 128
#define ED 16
#define SCAN_NBLK ((NN + 1023) / 1024)   // 49

// Scratch (allocation-free rule: __device__ globals)
__device__ float g_bufA[NN * DD];
__device__ float g_bufB[NN * DD];
__device__ int   g_idx64;
__device__ int   g_cnt[NN];
__device__ int   g_rowptr[NN + 1];
__device__ int   g_cursor[NN];
__device__ int   g_blocksum[SCAN_NBLK];
__device__ int   g_blockoff[SCAN_NBLK];
__device__ int   g_src[NE];              // src node, dst-sorted
__device__ float g_eattr[NE * ED];       // edge_attr rows in dst-sorted order

// ---------------------------------------------------------------------------
// Detect int64 vs int32 edge_idx (one warp, ballot)
// ---------------------------------------------------------------------------
__global__ void detect_idx_kernel(const long long* __restrict__ idx) {
    int lane = threadIdx.x;
    long long v = idx[lane];
    int bad = (v < 0 || v >= (long long)NN) ? 1 : 0;
    unsigned m = __ballot_sync(0xffffffffu, bad);
    if (lane == 0) g_idx64 = (m == 0u);
}

// ---------------------------------------------------------------------------
// CSR build
// ---------------------------------------------------------------------------
__global__ void zero_cnt_kernel() {
    int i = blockIdx.x * blockDim.x + threadIdx.x;
    if (i < NN) g_cnt[i] = 0;
}

__global__ void hist_kernel(const void* __restrict__ edge_idx) {
    int e = blockIdx.x * blockDim.x + threadIdx.x;
    if (e >= NE) return;
    int dst;
    if (g_idx64) dst = (int)((const long long*)edge_idx)[NE + e];
    else         dst = ((const int*)edge_idx)[NE + e];
    atomicAdd(&g_cnt[dst], 1);
}

__global__ void local_scan_kernel() {
    __shared__ int sdata[1024];
    int i = blockIdx.x * 1024 + threadIdx.x;
    int v = (i < NN) ? g_cnt[i] : 0;
    sdata[threadIdx.x] = v;
    __syncthreads();
    #pragma unroll
    for (int off = 1; off < 1024; off <<= 1) {
        int t = (threadIdx.x >= off) ? sdata[threadIdx.x - off] : 0;
        __syncthreads();
        sdata[threadIdx.x] += t;
        __syncthreads();
    }
    if (i < NN) g_rowptr[i] = sdata[threadIdx.x] - v;   // local exclusive
    if (threadIdx.x == 1023) g_blocksum[blockIdx.x] = sdata[1023];
}

__global__ void scan_sums_kernel() {
    __shared__ int sd[64];
    int t = threadIdx.x;
    int v = (t < SCAN_NBLK) ? g_blocksum[t] : 0;
    sd[t] = v;
    __syncthreads();
    #pragma unroll
    for (int off = 1; off < 64; off <<= 1) {
        int u = (t >= off) ? sd[t - off] : 0;
        __syncthreads();
        sd[t] += u;
        __syncthreads();
    }
    if (t < SCAN_NBLK) g_blockoff[t] = sd[t] - v;   // exclusive
}

__global__ void add_off_kernel() {
    int i = blockIdx.x * 1024 + threadIdx.x;
    if (i < NN) {
        int v = g_rowptr[i] + g_blockoff[blockIdx.x];
        g_rowptr[i] = v;
        g_cursor[i] = v;
    }
    if (i == 0) g_rowptr[NN] = NE;
}

// Fused scatter: place src AND the edge_attr row directly into dst-sorted
// order. edge_attr read is coalesced (thread e reads row e); write is random
// 64B (4x STG.128). Replaces the old scatter + gather_attr pair.
__global__ void scatter_fused_kernel(const void* __restrict__ edge_idx,
                                     const float* __restrict__ edge_attr) {
    int e = blockIdx.x * blockDim.x + threadIdx.x;
    if (e >= NE) return;
    int src, dst;
    if (g_idx64) {
        src = (int)((const long long*)edge_idx)[e];
        dst = (int)((const long long*)edge_idx)[NE + e];
    } else {
        src = ((const int*)edge_idx)[e];
        dst = ((const int*)edge_idx)[NE + e];
    }
    const float4* ea = (const float4*)(edge_attr + (size_t)e * ED);
    float4 a0 = ea[0], a1 = ea[1], a2 = ea[2], a3 = ea[3];
    int pos = atomicAdd(&g_cursor[dst], 1);
    g_src[pos] = src;
    float4* dstp = (float4*)(g_eattr + (size_t)pos * ED);
    dstp[0] = a0; dstp[1] = a1; dstp[2] = a2; dstp[3] = a3;
}

// ---------------------------------------------------------------------------
// Edge aggregation (CSR, no atomics): one warp per dst node.
// edge_attr pre-sorted (sequential reads); only x[src] is a gather.
// Edge loop unrolled by 2 (two independent memory chains).
// ---------------------------------------------------------------------------
#define MCHAIN(m, t0, t1, t2, t3)                                              \
    m.x += t0.x*w[0].x;  m.y += t0.x*w[0].y;  m.z += t0.x*w[0].z;  m.w += t0.x*w[0].w;  \
    m.x += t0.y*w[1].x;  m.y += t0.y*w[1].y;  m.z += t0.y*w[1].z;  m.w += t0.y*w[1].w;  \
    m.x += t0.z*w[2].x;  m.y += t0.z*w[2].y;  m.z += t0.z*w[2].z;  m.w += t0.z*w[2].w;  \
    m.x += t0.w*w[3].x;  m.y += t0.w*w[3].y;  m.z += t0.w*w[3].z;  m.w += t0.w*w[3].w;  \
    m.x += t1.x*w[4].x;  m.y += t1.x*w[4].y;  m.z += t1.x*w[4].z;  m.w += t1.x*w[4].w;  \
    m.x += t1.y*w[5].x;  m.y += t1.y*w[5].y;  m.z += t1.y*w[5].z;  m.w += t1.y*w[5].w;  \
    m.x += t1.z*w[6].x;  m.y += t1.z*w[6].y;  m.z += t1.z*w[6].z;  m.w += t1.z*w[6].w;  \
    m.x += t1.w*w[7].x;  m.y += t1.w*w[7].y;  m.z += t1.w*w[7].z;  m.w += t1.w*w[7].w;  \
    m.x += t2.x*w[8].x;  m.y += t2.x*w[8].y;  m.z += t2.x*w[8].z;  m.w += t2.x*w[8].w;  \
    m.x += t2.y*w[9].x;  m.y += t2.y*w[9].y;  m.z += t2.y*w[9].z;  m.w += t2.y*w[9].w;  \
    m.x += t2.z*w[10].x; m.y += t2.z*w[10].y; m.z += t2.z*w[10].z; m.w += t2.z*w[10].w; \
    m.x += t2.w*w[11].x; m.y += t2.w*w[11].y; m.z += t2.w*w[11].z; m.w += t2.w*w[11].w; \
    m.x += t3.x*w[12].x; m.y += t3.x*w[12].y; m.z += t3.x*w[12].z; m.w += t3.x*w[12].w; \
    m.x += t3.y*w[13].x; m.y += t3.y*w[13].y; m.z += t3.y*w[13].z; m.w += t3.y*w[13].w; \
    m.x += t3.z*w[14].x; m.y += t3.z*w[14].y; m.z += t3.z*w[14].z; m.w += t3.z*w[14].w; \
    m.x += t3.w*w[15].x; m.y += t3.w*w[15].y; m.z += t3.w*w[15].z; m.w += t3.w*w[15].w;

__global__ void __launch_bounds__(256)
aggr_kernel(const float* __restrict__ xin,
            const float* __restrict__ We,
            const float* __restrict__ be,
            const float* __restrict__ eps, int l,
            float* __restrict__ aggr) {
    int lane = threadIdx.x & 31;
    int warp = (blockIdx.x * blockDim.x + threadIdx.x) >> 5;
    int nwarps = (gridDim.x * blockDim.x) >> 5;
    int c0 = lane * 4;

    float4 w[ED];
    #pragma unroll
    for (int k = 0; k < ED; k++)
        w[k] = *(const float4*)(We + k * DD + c0);
    float4 bias = *(const float4*)(be + c0);
    float s = 1.0f + eps[l];

    for (int d = warp; d < NN; d += nwarps) {
        float4 xv = *(const float4*)(xin + (size_t)d * DD + c0);
        float4 acc = make_float4(xv.x * s, xv.y * s, xv.z * s, xv.w * s);
        int beg = g_rowptr[d], end = g_rowptr[d + 1];

        int j = beg;
        for (; j + 1 < end; j += 2) {
            int s0 = g_src[j];
            int s1 = g_src[j + 1];
            const float4* p0 = (const float4*)(g_eattr + (size_t)j * ED);
            float4 a0 = p0[0], a1 = p0[1], a2 = p0[2], a3 = p0[3];
            float4 b0 = p0[4], b1 = p0[5], b2 = p0[6], b3 = p0[7];
            float4 xs0 = *(const float4*)(xin + (size_t)s0 * DD + c0);
            float4 xs1 = *(const float4*)(xin + (size_t)s1 * DD + c0);

            float4 m0 = bias;
            MCHAIN(m0, a0, a1, a2, a3)
            float4 m1 = bias;
            MCHAIN(m1, b0, b1, b2, b3)

            acc.x += fmaxf(m0.x + xs0.x, 0.0f) + fmaxf(m1.x + xs1.x, 0.0f);
            acc.y += fmaxf(m0.y + xs0.y, 0.0f) + fmaxf(m1.y + xs1.y, 0.0f);
            acc.z += fmaxf(m0.z + xs0.z, 0.0f) + fmaxf(m1.z + xs1.z, 0.0f);
            acc.w += fmaxf(m0.w + xs0.w, 0.0f) + fmaxf(m1.w + xs1.w, 0.0f);
        }
        if (j < end) {
            int s0 = g_src[j];
            const float4* p0 = (const float4*)(g_eattr + (size_t)j * ED);
            float4 a0 = p0[0], a1 = p0[1], a2 = p0[2], a3 = p0[3];
            float4 xs0 = *(const float4*)(xin + (size_t)s0 * DD + c0);
            float4 m0 = bias;
            MCHAIN(m0, a0, a1, a2, a3)
            acc.x += fmaxf(m0.x + xs0.x, 0.0f);
            acc.y += fmaxf(m0.y + xs0.y, 0.0f);
            acc.z += fmaxf(m0.z + xs0.z, 0.0f);
            acc.w += fmaxf(m0.w + xs0.w, 0.0f);
        }
        *(float4*)(aggr + (size_t)d * DD + c0) = acc;
    }
}

// ---------------------------------------------------------------------------
// Fused node MLP, PERSISTENT: grid=148, each block loops over 128-row tiles.
// Weights/biases loaded into smem ONCE per block; no wave-quantization.
// C = gelu_exact(A @ W1 + b1) @ W2 + b2, 8x8 register tiles, 256 threads.
// ---------------------------------------------------------------------------
#define SA_PITCH 132
#define MLP_TILES ((NN + 127) / 128)     // 391
#define MLP_SMEM_FLOATS (128 * SA_PITCH + 2 * 128 * 128 + 256)
#define MLP_SMEM_BYTES (MLP_SMEM_FLOATS * 4)

__global__ void __launch_bounds__(256)
mlp_kernel(const float* __restrict__ A,
           const float* __restrict__ W1g,
           const float* __restrict__ b1g,
           const float* __restrict__ W2g,
           const float* __restrict__ b2g,
           float* __restrict__ C) {
    extern __shared__ float sm[];
    float* sA  = sm;                      // 128 x 132 (padded)
    float* sW1 = sm + 128 * SA_PITCH;     // 128 x 128
    float* sW2 = sW1 + 128 * 128;         // 128 x 128
    float* sb1 = sW2 + 128 * 128;         // 128
    float* sb2 = sb1 + 128;               // 128

    int tid = threadIdx.x;

    // one-time weight + bias load
    for (int i = tid; i < 128 * 32; i += 256) {
        ((float4*)sW1)[i] = ((const float4*)W1g)[i];
        ((float4*)sW2)[i] = ((const float4*)W2g)[i];
    }
    if (tid < 128) { sb1[tid] = b1g[tid]; sb2[tid] = b2g[tid]; }

    int tx = tid & 15, ty = tid >> 4;
    int r0 = ty * 8, cc = tx * 8;

    for (int tile = blockIdx.x; tile < MLP_TILES; tile += gridDim.x) {
        int row0 = tile * 128;

        __syncthreads();   // previous iteration done reading sA
        for (int i = tid; i < 128 * 32; i += 256) {
            int r = i >> 5, k4 = i & 31;
            int gr = row0 + r;
            float4 v = (gr < NN) ? ((const float4*)(A + (size_t)gr * DD))[k4]
                                 : make_float4(0.f, 0.f, 0.f, 0.f);
            *(float4*)(sA + r * SA_PITCH + k4 * 4) = v;
        }
        __syncthreads();

        float acc[8][8];
        #pragma unroll
        for (int i = 0; i < 8; i++)
            #pragma unroll
            for (int j = 0; j < 8; j++) acc[i][j] = 0.0f;

        // GEMM1: acc = A @ W1
        #pragma unroll 4
        for (int k = 0; k < 128; k++) {
            float4 wa = *(const float4*)(sW1 + k * 128 + cc);
            float4 wb = *(const float4*)(sW1 + k * 128 + cc + 4);
            float a[8];
            #pragma unroll
            for (int i = 0; i < 8; i++) a[i] = sA[(r0 + i) * SA_PITCH + k];
            #pragma unroll
            for (int i = 0; i < 8; i++) {
                acc[i][0] += a[i] * wa.x; acc[i][1] += a[i] * wa.y;
                acc[i][2] += a[i] * wa.z; acc[i][3] += a[i] * wa.w;
                acc[i][4] += a[i] * wb.x; acc[i][5] += a[i] * wb.y;
                acc[i][6] += a[i] * wb.z; acc[i][7] += a[i] * wb.w;
            }
        }
        __syncthreads();

        // H = gelu_exact(acc + b1) -> sA ; reset acc
        #pragma unroll
        for (int i = 0; i < 8; i++) {
            #pragma unroll
            for (int j = 0; j < 8; j++) {
                float h = acc[i][j] + sb1[cc + j];
                h = 0.5f * h * (1.0f + erff(h * 0.70710678118654752f));
                sA[(r0 + i) * SA_PITCH + cc + j] = h;
                acc[i][j] = 0.0f;
            }
        }
        __syncthreads();

        // GEMM2: acc = H @ W2
        #pragma unroll 4
        for (int k = 0; k < 128; k++) {
            float4 wa = *(const float4*)(sW2 + k * 128 + cc);
            float4 wb = *(const float4*)(sW2 + k * 128 + cc + 4);
            float a[8];
            #pragma unroll
            for (int i = 0; i < 8; i++) a[i] = sA[(r0 + i) * SA_PITCH + k];
            #pragma unroll
            for (int i = 0; i < 8; i++) {
                acc[i][0] += a[i] * wa.x; acc[i][1] += a[i] * wa.y;
                acc[i][2] += a[i] * wa.z; acc[i][3] += a[i] * wa.w;
                acc[i][4] += a[i] * wb.x; acc[i][5] += a[i] * wb.y;
                acc[i][6] += a[i] * wb.z; acc[i][7] += a[i] * wb.w;
            }
        }

        // bias + store
        #pragma unroll
        for (int i = 0; i < 8; i++) {
            int gr = row0 + r0 + i;
            if (gr < NN) {
                float4 o0 = make_float4(acc[i][0] + sb2[cc],     acc[i][1] + sb2[cc + 1],
                                        acc[i][2] + sb2[cc + 2], acc[i][3] + sb2[cc + 3]);
                float4 o1 = make_float4(acc[i][4] + sb2[cc + 4], acc[i][5] + sb2[cc + 5],
                                        acc[i][6] + sb2[cc + 6], acc[i][7] + sb2[cc + 7]);
                *(float4*)(C + (size_t)gr * DD + cc) = o0;
                *(float4*)(C + (size_t)gr * DD + cc + 4) = o1;
            }
        }
    }
}

// ---------------------------------------------------------------------------
// Launch
// ---------------------------------------------------------------------------
extern "C" void kernel_launch(void* const* d_in, const int* in_sizes, int n_in,
                              void* d_out, int out_size) {
    const float* x         = (const float*)d_in[0];
    const float* edge_attr = (const float*)d_in[1];
    const float* W1        = (const float*)d_in[2];
    const float* b1        = (const float*)d_in[3];
    const float* W2        = (const float*)d_in[4];
    const float* b2        = (const float*)d_in[5];
    const float* We        = (const float*)d_in[6];
    const float* be        = (const float*)d_in[7];
    const float* eps       = (const float*)d_in[8];
    const void*  edge_idx  = d_in[9];
    float* out = (float*)d_out;

    float *bufA, *bufB;
    cudaGetSymbolAddress((void**)&bufA, g_bufA);
    cudaGetSymbolAddress((void**)&bufB, g_bufB);

    cudaFuncSetAttribute(mlp_kernel,
                         cudaFuncAttributeMaxDynamicSharedMemorySize,
                         MLP_SMEM_BYTES);

    // ---- CSR build + attr pre-sort (once per launch) ----
    detect_idx_kernel<<<1, 32>>>((const long long*)edge_idx);
    zero_cnt_kernel<<<(NN + 255) / 256, 256>>>();
    hist_kernel<<<(NE + 255) / 256, 256>>>(edge_idx);
    local_scan_kernel<<<SCAN_NBLK, 1024>>>();
    scan_sums_kernel<<<1, 64>>>();
    add_off_kernel<<<SCAN_NBLK, 1024>>>();
    scatter_fused_kernel<<<(NE + 255) / 256, 256>>>(edge_idx, edge_attr);

    const int aggr_blocks = (NN * 32 + 255) / 256;   // one warp per node

    const float* xin = x;
    for (int l = 0; l < 3; l++) {
        float* aggr = (l == 1) ? bufB : bufA;
        float* xout = (l == 0) ? bufA : ((l == 1) ? bufB : out);

        aggr_kernel<<<aggr_blocks, 256>>>(xin, We + l * ED * DD,
                                          be + l * DD, eps, l, aggr);
        mlp_kernel<<<148, 256, MLP_SMEM_BYTES>>>(
            aggr, W1 + l * DD * DD, b1 + l * DD,
            W2 + l * DD * DD, b2 + l * DD, xout);
        xin = xout;
    }
}

// round 8
// speedup vs baseline: 1.1985x; 1.0920x over previous
#include <cuda_runtime.h>
#include <math.h>

#define NN 50000
#define NE 800000
#define DD 128
#define ED 16
#define SCAN_NBLK ((NN + 1023) / 1024)   // 49

// Scratch (allocation-free rule: __device__ globals)
__device__ float g_bufA[NN * DD];
__device__ float g_bufB[NN * DD];
__device__ int   g_idx64;
__device__ int   g_cnt[NN];
__device__ int   g_rowptr[NN + 1];
__device__ int   g_cursor[NN];
__device__ int   g_blocksum[SCAN_NBLK];
__device__ int   g_blockoff[SCAN_NBLK];
__device__ int   g_src[NE];              // src node, dst-sorted
__device__ float g_eattr[NE * ED];       // edge_attr rows in dst-sorted order

// ---------------------------------------------------------------------------
// tf32 helpers
// ---------------------------------------------------------------------------
__device__ __forceinline__ void tf32split(float v, unsigned& hi, unsigned& lo) {
    asm("cvt.rna.tf32.f32 %0, %1;" : "=r"(hi) : "f"(v));
    float r = v - __uint_as_float(hi);
    asm("cvt.rna.tf32.f32 %0, %1;" : "=r"(lo) : "f"(r));
}

__device__ __forceinline__ void mma_tf32(float* d, const unsigned* a, const unsigned* b) {
    asm volatile(
        "mma.sync.aligned.m16n8k8.row.col.f32.tf32.tf32.f32 "
        "{%0,%1,%2,%3}, {%4,%5,%6,%7}, {%8,%9}, {%0,%1,%2,%3};"
        : "+f"(d[0]), "+f"(d[1]), "+f"(d[2]), "+f"(d[3])
        : "r"(a[0]), "r"(a[1]), "r"(a[2]), "r"(a[3]), "r"(b[0]), "r"(b[1]));
}

// ---------------------------------------------------------------------------
// Detect int64 vs int32 edge_idx (one warp, ballot)
// ---------------------------------------------------------------------------
__global__ void detect_idx_kernel(const long long* __restrict__ idx) {
    int lane = threadIdx.x;
    long long v = idx[lane];
    int bad = (v < 0 || v >= (long long)NN) ? 1 : 0;
    unsigned m = __ballot_sync(0xffffffffu, bad);
    if (lane == 0) g_idx64 = (m == 0u);
}

// ---------------------------------------------------------------------------
// CSR build
// ---------------------------------------------------------------------------
__global__ void zero_cnt_kernel() {
    int i = blockIdx.x * blockDim.x + threadIdx.x;
    if (i < NN) g_cnt[i] = 0;
}

__global__ void hist_kernel(const void* __restrict__ edge_idx) {
    int e = blockIdx.x * blockDim.x + threadIdx.x;
    if (e >= NE) return;
    int dst;
    if (g_idx64) dst = (int)((const long long*)edge_idx)[NE + e];
    else         dst = ((const int*)edge_idx)[NE + e];
    atomicAdd(&g_cnt[dst], 1);
}

__global__ void local_scan_kernel() {
    __shared__ int sdata[1024];
    int i = blockIdx.x * 1024 + threadIdx.x;
    int v = (i < NN) ? g_cnt[i] : 0;
    sdata[threadIdx.x] = v;
    __syncthreads();
    #pragma unroll
    for (int off = 1; off < 1024; off <<= 1) {
        int t = (threadIdx.x >= off) ? sdata[threadIdx.x - off] : 0;
        __syncthreads();
        sdata[threadIdx.x] += t;
        __syncthreads();
    }
    if (i < NN) g_rowptr[i] = sdata[threadIdx.x] - v;   // local exclusive
    if (threadIdx.x == 1023) g_blocksum[blockIdx.x] = sdata[1023];
}

__global__ void scan_sums_kernel() {
    __shared__ int sd[64];
    int t = threadIdx.x;
    int v = (t < SCAN_NBLK) ? g_blocksum[t] : 0;
    sd[t] = v;
    __syncthreads();
    #pragma unroll
    for (int off = 1; off < 64; off <<= 1) {
        int u = (t >= off) ? sd[t - off] : 0;
        __syncthreads();
        sd[t] += u;
        __syncthreads();
    }
    if (t < SCAN_NBLK) g_blockoff[t] = sd[t] - v;   // exclusive
}

__global__ void add_off_kernel() {
    int i = blockIdx.x * 1024 + threadIdx.x;
    if (i < NN) {
        int v = g_rowptr[i] + g_blockoff[blockIdx.x];
        g_rowptr[i] = v;
        g_cursor[i] = v;
    }
    if (i == 0) g_rowptr[NN] = NE;
}

// Fused scatter: place src AND the edge_attr row directly into dst-sorted order.
__global__ void scatter_fused_kernel(const void* __restrict__ edge_idx,
                                     const float* __restrict__ edge_attr) {
    int e = blockIdx.x * blockDim.x + threadIdx.x;
    if (e >= NE) return;
    int src, dst;
    if (g_idx64) {
        src = (int)((const long long*)edge_idx)[e];
        dst = (int)((const long long*)edge_idx)[NE + e];
    } else {
        src = ((const int*)edge_idx)[e];
        dst = ((const int*)edge_idx)[NE + e];
    }
    const float4* ea = (const float4*)(edge_attr + (size_t)e * ED);
    float4 a0 = ea[0], a1 = ea[1], a2 = ea[2], a3 = ea[3];
    int pos = atomicAdd(&g_cursor[dst], 1);
    g_src[pos] = src;
    float4* dstp = (float4*)(g_eattr + (size_t)pos * ED);
    dstp[0] = a0; dstp[1] = a1; dstp[2] = a2; dstp[3] = a3;
}

// ---------------------------------------------------------------------------
// Edge aggregation (CSR, no atomics): one warp per dst node (unchanged, R6).
// ---------------------------------------------------------------------------
#define MCHAIN(m, t0, t1, t2, t3)                                              \
    m.x += t0.x*w[0].x;  m.y += t0.x*w[0].y;  m.z += t0.x*w[0].z;  m.w += t0.x*w[0].w;  \
    m.x += t0.y*w[1].x;  m.y += t0.y*w[1].y;  m.z += t0.y*w[1].z;  m.w += t0.y*w[1].w;  \
    m.x += t0.z*w[2].x;  m.y += t0.z*w[2].y;  m.z += t0.z*w[2].z;  m.w += t0.z*w[2].w;  \
    m.x += t0.w*w[3].x;  m.y += t0.w*w[3].y;  m.z += t0.w*w[3].z;  m.w += t0.w*w[3].w;  \
    m.x += t1.x*w[4].x;  m.y += t1.x*w[4].y;  m.z += t1.x*w[4].z;  m.w += t1.x*w[4].w;  \
    m.x += t1.y*w[5].x;  m.y += t1.y*w[5].y;  m.z += t1.y*w[5].z;  m.w += t1.y*w[5].w;  \
    m.x += t1.z*w[6].x;  m.y += t1.z*w[6].y;  m.z += t1.z*w[6].z;  m.w += t1.z*w[6].w;  \
    m.x += t1.w*w[7].x;  m.y += t1.w*w[7].y;  m.z += t1.w*w[7].z;  m.w += t1.w*w[7].w;  \
    m.x += t2.x*w[8].x;  m.y += t2.x*w[8].y;  m.z += t2.x*w[8].z;  m.w += t2.x*w[8].w;  \
    m.x += t2.y*w[9].x;  m.y += t2.y*w[9].y;  m.z += t2.y*w[9].z;  m.w += t2.y*w[9].w;  \
    m.x += t2.z*w[10].x; m.y += t2.z*w[10].y; m.z += t2.z*w[10].z; m.w += t2.z*w[10].w; \
    m.x += t2.w*w[11].x; m.y += t2.w*w[11].y; m.z += t2.w*w[11].z; m.w += t2.w*w[11].w; \
    m.x += t3.x*w[12].x; m.y += t3.x*w[12].y; m.z += t3.x*w[12].z; m.w += t3.x*w[12].w; \
    m.x += t3.y*w[13].x; m.y += t3.y*w[13].y; m.z += t3.y*w[13].z; m.w += t3.y*w[13].w; \
    m.x += t3.z*w[14].x; m.y += t3.z*w[14].y; m.z += t3.z*w[14].z; m.w += t3.z*w[14].w; \
    m.x += t3.w*w[15].x; m.y += t3.w*w[15].y; m.z += t3.w*w[15].z; m.w += t3.w*w[15].w;

__global__ void __launch_bounds__(256)
aggr_kernel(const float* __restrict__ xin,
            const float* __restrict__ We,
            const float* __restrict__ be,
            const float* __restrict__ eps, int l,
            float* __restrict__ aggr) {
    int lane = threadIdx.x & 31;
    int warp = (blockIdx.x * blockDim.x + threadIdx.x) >> 5;
    int nwarps = (gridDim.x * blockDim.x) >> 5;
    int c0 = lane * 4;

    float4 w[ED];
    #pragma unroll
    for (int k = 0; k < ED; k++)
        w[k] = *(const float4*)(We + k * DD + c0);
    float4 bias = *(const float4*)(be + c0);
    float s = 1.0f + eps[l];

    for (int d = warp; d < NN; d += nwarps) {
        float4 xv = *(const float4*)(xin + (size_t)d * DD + c0);
        float4 acc = make_float4(xv.x * s, xv.y * s, xv.z * s, xv.w * s);
        int beg = g_rowptr[d], end = g_rowptr[d + 1];

        int j = beg;
        for (; j + 1 < end; j += 2) {
            int s0 = g_src[j];
            int s1 = g_src[j + 1];
            const float4* p0 = (const float4*)(g_eattr + (size_t)j * ED);
            float4 a0 = p0[0], a1 = p0[1], a2 = p0[2], a3 = p0[3];
            float4 b0 = p0[4], b1 = p0[5], b2 = p0[6], b3 = p0[7];
            float4 xs0 = *(const float4*)(xin + (size_t)s0 * DD + c0);
            float4 xs1 = *(const float4*)(xin + (size_t)s1 * DD + c0);

            float4 m0 = bias;
            MCHAIN(m0, a0, a1, a2, a3)
            float4 m1 = bias;
            MCHAIN(m1, b0, b1, b2, b3)

            acc.x += fmaxf(m0.x + xs0.x, 0.0f) + fmaxf(m1.x + xs1.x, 0.0f);
            acc.y += fmaxf(m0.y + xs0.y, 0.0f) + fmaxf(m1.y + xs1.y, 0.0f);
            acc.z += fmaxf(m0.z + xs0.z, 0.0f) + fmaxf(m1.z + xs1.z, 0.0f);
            acc.w += fmaxf(m0.w + xs0.w, 0.0f) + fmaxf(m1.w + xs1.w, 0.0f);
        }
        if (j < end) {
            int s0 = g_src[j];
            const float4* p0 = (const float4*)(g_eattr + (size_t)j * ED);
            float4 a0 = p0[0], a1 = p0[1], a2 = p0[2], a3 = p0[3];
            float4 xs0 = *(const float4*)(xin + (size_t)s0 * DD + c0);
            float4 m0 = bias;
            MCHAIN(m0, a0, a1, a2, a3)
            acc.x += fmaxf(m0.x + xs0.x, 0.0f);
            acc.y += fmaxf(m0.y + xs0.y, 0.0f);
            acc.z += fmaxf(m0.z + xs0.z, 0.0f);
            acc.w += fmaxf(m0.w + xs0.w, 0.0f);
        }
        *(float4*)(aggr + (size_t)d * DD + c0) = acc;
    }
}

// ---------------------------------------------------------------------------
// Fused node MLP with tf32 tensor cores (3-way split = fp32-grade accuracy).
// Persistent, grid=148, 256 threads (8 warps).
// CORRECTED PTX fragment layouts (m16n8k8, g=lane>>2, c=lane&3):
//   A: a0=(g, c)   a1=(g+8, c)   a2=(g, c+4)   a3=(g+8, c+4)   [row, k]
//   B: b0=(k=c, n) b1=(k=c+4, n) with n = this thread's g      [col-major]
//   C: c0=(g,2c) c1=(g,2c+1) c2=(g+8,2c) c3=(g+8,2c+1)
// Weights stored transposed ([n][k]) in smem; pitch 132 -> bank = 4g+c,
// all 32 banks distinct (conflict-free).
// Warp tiling: warp (wm=w%4, wn=w/4): rows wm*32..+31, cols wn*64..+63.
// ---------------------------------------------------------------------------
#define PITCH 132
#define MLP_TILES ((NN + 127) / 128)     // 391
#define MLP_SMEM_FLOATS (3 * 128 * PITCH + 256)
#define MLP_SMEM_BYTES (MLP_SMEM_FLOATS * 4)

__global__ void __launch_bounds__(256)
mlp_kernel(const float* __restrict__ A,
           const float* __restrict__ W1g,
           const float* __restrict__ b1g,
           const float* __restrict__ W2g,
           const float* __restrict__ b2g,
           float* __restrict__ C) {
    extern __shared__ float sm[];
    float* sA   = sm;                     // 128 x 132 (A tile, then H)
    float* sW1T = sm + 128 * PITCH;       // W1^T : [n][k]
    float* sW2T = sW1T + 128 * PITCH;     // W2^T : [n][k]
    float* sb1  = sW2T + 128 * PITCH;     // 128
    float* sb2  = sb1 + 128;              // 128

    int tid = threadIdx.x;

    // One-time: transposed weight + bias load
    for (int i = tid; i < 128 * 128; i += 256) {
        int k = i >> 7, n = i & 127;      // read coalesced over n
        sW1T[n * PITCH + k] = W1g[i];
        sW2T[n * PITCH + k] = W2g[i];
    }
    if (tid < 128) { sb1[tid] = b1g[tid]; sb2[tid] = b2g[tid]; }

    int lane = tid & 31, wid = tid >> 5;
    int g = lane >> 2, c = lane & 3;      // groupID, tid-in-group
    int wm = wid & 3, wn = wid >> 2;      // warp grid 4 x 2
    int mrow = wm * 32;                   // warp's row base within tile
    int ncol = wn * 64;                   // warp's col base

    for (int tile = blockIdx.x; tile < MLP_TILES; tile += gridDim.x) {
        int row0 = tile * 128;

        __syncthreads();   // previous iteration done reading sA
        for (int i = tid; i < 128 * 32; i += 256) {
            int r = i >> 5, k4 = i & 31;
            int gr = row0 + r;
            float4 v = (gr < NN) ? ((const float4*)(A + (size_t)gr * DD))[k4]
                                 : make_float4(0.f, 0.f, 0.f, 0.f);
            *(float4*)(sA + r * PITCH + k4 * 4) = v;
        }
        __syncthreads();

        float acc[2][8][4];
        #pragma unroll
        for (int mt = 0; mt < 2; mt++)
            #pragma unroll
            for (int j = 0; j < 8; j++)
                #pragma unroll
                for (int q = 0; q < 4; q++) acc[mt][j][q] = 0.0f;

        // ---- GEMM1: A @ W1 ----
        #pragma unroll 1
        for (int s = 0; s < 16; s++) {
            int k0 = s * 8;
            unsigned bhi[8][2], blo[8][2];
            #pragma unroll
            for (int j = 0; j < 8; j++) {
                const float* bp = sW1T + (ncol + 8 * j + g) * PITCH + k0;
                tf32split(bp[c],     bhi[j][0], blo[j][0]);   // k = c
                tf32split(bp[c + 4], bhi[j][1], blo[j][1]);   // k = c+4
            }
            #pragma unroll
            for (int mt = 0; mt < 2; mt++) {
                int r = mrow + mt * 16 + g;
                const float* arow0 = sA + r * PITCH + k0;
                const float* arow1 = sA + (r + 8) * PITCH + k0;
                unsigned ahi[4], alo[4];
                tf32split(arow0[c],     ahi[0], alo[0]);   // (g,   c)
                tf32split(arow1[c],     ahi[1], alo[1]);   // (g+8, c)
                tf32split(arow0[c + 4], ahi[2], alo[2]);   // (g,   c+4)
                tf32split(arow1[c + 4], ahi[3], alo[3]);   // (g+8, c+4)
                #pragma unroll
                for (int j = 0; j < 8; j++) {
                    mma_tf32(acc[mt][j], ahi, bhi[j]);
                    mma_tf32(acc[mt][j], ahi, blo[j]);
                    mma_tf32(acc[mt][j], alo, bhi[j]);
                }
            }
        }
        __syncthreads();   // all warps done reading sA

        // ---- epilogue 1: H = gelu_exact(D1 + b1) -> sA ----
        #pragma unroll
        for (int mt = 0; mt < 2; mt++) {
            int r = mrow + mt * 16 + g;
            #pragma unroll
            for (int j = 0; j < 8; j++) {
                int col = ncol + 8 * j + 2 * c;
                float h0 = acc[mt][j][0] + sb1[col];
                float h1 = acc[mt][j][1] + sb1[col + 1];
                float h2 = acc[mt][j][2] + sb1[col];
                float h3 = acc[mt][j][3] + sb1[col + 1];
                h0 = 0.5f * h0 * (1.0f + erff(h0 * 0.70710678118654752f));
                h1 = 0.5f * h1 * (1.0f + erff(h1 * 0.70710678118654752f));
                h2 = 0.5f * h2 * (1.0f + erff(h2 * 0.70710678118654752f));
                h3 = 0.5f * h3 * (1.0f + erff(h3 * 0.70710678118654752f));
                *(float2*)(sA + r * PITCH + col) = make_float2(h0, h1);
                *(float2*)(sA + (r + 8) * PITCH + col) = make_float2(h2, h3);
                acc[mt][j][0] = 0.0f; acc[mt][j][1] = 0.0f;
                acc[mt][j][2] = 0.0f; acc[mt][j][3] = 0.0f;
            }
        }
        __syncthreads();

        // ---- GEMM2: H @ W2 ----
        #pragma unroll 1
        for (int s = 0; s < 16; s++) {
            int k0 = s * 8;
            unsigned bhi[8][2], blo[8][2];
            #pragma unroll
            for (int j = 0; j < 8; j++) {
                const float* bp = sW2T + (ncol + 8 * j + g) * PITCH + k0;
                tf32split(bp[c],     bhi[j][0], blo[j][0]);
                tf32split(bp[c + 4], bhi[j][1], blo[j][1]);
            }
            #pragma unroll
            for (int mt = 0; mt < 2; mt++) {
                int r = mrow + mt * 16 + g;
                const float* arow0 = sA + r * PITCH + k0;
                const float* arow1 = sA + (r + 8) * PITCH + k0;
                unsigned ahi[4], alo[4];
                tf32split(arow0[c],     ahi[0], alo[0]);
                tf32split(arow1[c],     ahi[1], alo[1]);
                tf32split(arow0[c + 4], ahi[2], alo[2]);
                tf32split(arow1[c + 4], ahi[3], alo[3]);
                #pragma unroll
                for (int j = 0; j < 8; j++) {
                    mma_tf32(acc[mt][j], ahi, bhi[j]);
                    mma_tf32(acc[mt][j], ahi, blo[j]);
                    mma_tf32(acc[mt][j], alo, bhi[j]);
                }
            }
        }

        // ---- epilogue 2: C = D2 + b2 ----
        #pragma unroll
        for (int mt = 0; mt < 2; mt++) {
            int r = mrow + mt * 16 + g;
            int gr0 = row0 + r, gr1 = row0 + r + 8;
            #pragma unroll
            for (int j = 0; j < 8; j++) {
                int col = ncol + 8 * j + 2 * c;
                if (gr0 < NN)
                    *(float2*)(C + (size_t)gr0 * DD + col) =
                        make_float2(acc[mt][j][0] + sb2[col],
                                    acc[mt][j][1] + sb2[col + 1]);
                if (gr1 < NN)
                    *(float2*)(C + (size_t)gr1 * DD + col) =
                        make_float2(acc[mt][j][2] + sb2[col],
                                    acc[mt][j][3] + sb2[col + 1]);
            }
        }
    }
}

// ---------------------------------------------------------------------------
// Launch
// ---------------------------------------------------------------------------
extern "C" void kernel_launch(void* const* d_in, const int* in_sizes, int n_in,
                              void* d_out, int out_size) {
    const float* x         = (const float*)d_in[0];
    const float* edge_attr = (const float*)d_in[1];
    const float* W1        = (const float*)d_in[2];
    const float* b1        = (const float*)d_in[3];
    const float* W2        = (const float*)d_in[4];
    const float* b2        = (const float*)d_in[5];
    const float* We        = (const float*)d_in[6];
    const float* be        = (const float*)d_in[7];
    const float* eps       = (const float*)d_in[8];
    const void*  edge_idx  = d_in[9];
    float* out = (float*)d_out;

    float *bufA, *bufB;
    cudaGetSymbolAddress((void**)&bufA, g_bufA);
    cudaGetSymbolAddress((void**)&bufB, g_bufB);

    cudaFuncSetAttribute(mlp_kernel,
                         cudaFuncAttributeMaxDynamicSharedMemorySize,
                         MLP_SMEM_BYTES);

    // ---- CSR build + attr pre-sort (once per launch) ----
    detect_idx_kernel<<<1, 32>>>((const long long*)edge_idx);
    zero_cnt_kernel<<<(NN + 255) / 256, 256>>>();
    hist_kernel<<<(NE + 255) / 256, 256>>>(edge_idx);
    local_scan_kernel<<<SCAN_NBLK, 1024>>>();
    scan_sums_kernel<<<1, 64>>>();
    add_off_kernel<<<SCAN_NBLK, 1024>>>();
    scatter_fused_kernel<<<(NE + 255) / 256, 256>>>(edge_idx, edge_attr);

    const int aggr_blocks = (NN * 32 + 255) / 256;   // one warp per node

    const float* xin = x;
    for (int l = 0; l < 3; l++) {
        float* aggr = (l == 1) ? bufB : bufA;
        float* xout = (l == 0) ? bufA : ((l == 1) ? bufB : out);

        aggr_kernel<<<aggr_blocks, 256>>>(xin, We + l * ED * DD,
                                          be + l * DD, eps, l, aggr);
        mlp_kernel<<<148, 256, MLP_SMEM_BYTES>>>(
            aggr, W1 + l * DD * DD, b1 + l * DD,
            W2 + l * DD * DD, b2 + l * DD, xout);
        xin = xout;
    }
}

// round 9
// speedup vs baseline: 1.2087x; 1.0085x over previous
#include <cuda_runtime.h>
#include <math.h>

#define NN 50000
#define NE 800000
#define DD 128
#define ED 16
#define SCAN_NBLK ((NN + 1023) / 1024)   // 49

// Scratch (allocation-free rule: __device__ globals)
__device__ float g_bufA[NN * DD];
__device__ float g_bufB[NN * DD];
__device__ int   g_idx64;
__device__ int   g_cnt[NN];
__device__ int   g_rowptr[NN + 1];
__device__ int   g_cursor[NN];
__device__ int   g_blocksum[SCAN_NBLK];
__device__ int   g_blockoff[SCAN_NBLK];
__device__ int   g_src[NE];              // src node, dst-sorted
__device__ float g_eattr[NE * ED];       // edge_attr rows in dst-sorted order

// ---------------------------------------------------------------------------
// tf32 helpers
// ---------------------------------------------------------------------------
__device__ __forceinline__ void tf32split(float v, unsigned& hi, unsigned& lo) {
    asm("cvt.rna.tf32.f32 %0, %1;" : "=r"(hi) : "f"(v));
    float r = v - __uint_as_float(hi);
    asm("cvt.rna.tf32.f32 %0, %1;" : "=r"(lo) : "f"(r));
}

__device__ __forceinline__ void mma_tf32(float* d, const unsigned* a, const unsigned* b) {
    asm volatile(
        "mma.sync.aligned.m16n8k8.row.col.f32.tf32.tf32.f32 "
        "{%0,%1,%2,%3}, {%4,%5,%6,%7}, {%8,%9}, {%0,%1,%2,%3};"
        : "+f"(d[0]), "+f"(d[1]), "+f"(d[2]), "+f"(d[3])
        : "r"(a[0]), "r"(a[1]), "r"(a[2]), "r"(a[3]), "r"(b[0]), "r"(b[1]));
}

// ---------------------------------------------------------------------------
// Detect int64 vs int32 edge_idx (one warp, ballot)
// ---------------------------------------------------------------------------
__global__ void detect_idx_kernel(const long long* __restrict__ idx) {
    int lane = threadIdx.x;
    long long v = idx[lane];
    int bad = (v < 0 || v >= (long long)NN) ? 1 : 0;
    unsigned m = __ballot_sync(0xffffffffu, bad);
    if (lane == 0) g_idx64 = (m == 0u);
}

// ---------------------------------------------------------------------------
// CSR build
// ---------------------------------------------------------------------------
__global__ void zero_cnt_kernel() {
    int i = blockIdx.x * blockDim.x + threadIdx.x;
    if (i < NN) g_cnt[i] = 0;
}

__global__ void hist_kernel(const void* __restrict__ edge_idx) {
    int e = blockIdx.x * blockDim.x + threadIdx.x;
    if (e >= NE) return;
    int dst;
    if (g_idx64) dst = (int)((const long long*)edge_idx)[NE + e];
    else         dst = ((const int*)edge_idx)[NE + e];
    atomicAdd(&g_cnt[dst], 1);
}

__global__ void local_scan_kernel() {
    __shared__ int sdata[1024];
    int i = blockIdx.x * 1024 + threadIdx.x;
    int v = (i < NN) ? g_cnt[i] : 0;
    sdata[threadIdx.x] = v;
    __syncthreads();
    #pragma unroll
    for (int off = 1; off < 1024; off <<= 1) {
        int t = (threadIdx.x >= off) ? sdata[threadIdx.x - off] : 0;
        __syncthreads();
        sdata[threadIdx.x] += t;
        __syncthreads();
    }
    if (i < NN) g_rowptr[i] = sdata[threadIdx.x] - v;   // local exclusive
    if (threadIdx.x == 1023) g_blocksum[blockIdx.x] = sdata[1023];
}

__global__ void scan_sums_kernel() {
    __shared__ int sd[64];
    int t = threadIdx.x;
    int v = (t < SCAN_NBLK) ? g_blocksum[t] : 0;
    sd[t] = v;
    __syncthreads();
    #pragma unroll
    for (int off = 1; off < 64; off <<= 1) {
        int u = (t >= off) ? sd[t - off] : 0;
        __syncthreads();
        sd[t] += u;
        __syncthreads();
    }
    if (t < SCAN_NBLK) g_blockoff[t] = sd[t] - v;   // exclusive
}

__global__ void add_off_kernel() {
    int i = blockIdx.x * 1024 + threadIdx.x;
    if (i < NN) {
        int v = g_rowptr[i] + g_blockoff[blockIdx.x];
        g_rowptr[i] = v;
        g_cursor[i] = v;
    }
    if (i == 0) g_rowptr[NN] = NE;
}

// Fused scatter: place src AND the edge_attr row directly into dst-sorted order.
__global__ void scatter_fused_kernel(const void* __restrict__ edge_idx,
                                     const float* __restrict__ edge_attr) {
    int e = blockIdx.x * blockDim.x + threadIdx.x;
    if (e >= NE) return;
    int src, dst;
    if (g_idx64) {
        src = (int)((const long long*)edge_idx)[e];
        dst = (int)((const long long*)edge_idx)[NE + e];
    } else {
        src = ((const int*)edge_idx)[e];
        dst = ((const int*)edge_idx)[NE + e];
    }
    const float4* ea = (const float4*)(edge_attr + (size_t)e * ED);
    float4 a0 = ea[0], a1 = ea[1], a2 = ea[2], a3 = ea[3];
    int pos = atomicAdd(&g_cursor[dst], 1);
    g_src[pos] = src;
    float4* dstp = (float4*)(g_eattr + (size_t)pos * ED);
    dstp[0] = a0; dstp[1] = a1; dstp[2] = a2; dstp[3] = a3;
}

// ---------------------------------------------------------------------------
// Edge aggregation (CSR, no atomics): one warp per dst node (unchanged, R6).
// ---------------------------------------------------------------------------
#define MCHAIN(m, t0, t1, t2, t3)                                              \
    m.x += t0.x*w[0].x;  m.y += t0.x*w[0].y;  m.z += t0.x*w[0].z;  m.w += t0.x*w[0].w;  \
    m.x += t0.y*w[1].x;  m.y += t0.y*w[1].y;  m.z += t0.y*w[1].z;  m.w += t0.y*w[1].w;  \
    m.x += t0.z*w[2].x;  m.y += t0.z*w[2].y;  m.z += t0.z*w[2].z;  m.w += t0.z*w[2].w;  \
    m.x += t0.w*w[3].x;  m.y += t0.w*w[3].y;  m.z += t0.w*w[3].z;  m.w += t0.w*w[3].w;  \
    m.x += t1.x*w[4].x;  m.y += t1.x*w[4].y;  m.z += t1.x*w[4].z;  m.w += t1.x*w[4].w;  \
    m.x += t1.y*w[5].x;  m.y += t1.y*w[5].y;  m.z += t1.y*w[5].z;  m.w += t1.y*w[5].w;  \
    m.x += t1.z*w[6].x;  m.y += t1.z*w[6].y;  m.z += t1.z*w[6].z;  m.w += t1.z*w[6].w;  \
    m.x += t1.w*w[7].x;  m.y += t1.w*w[7].y;  m.z += t1.w*w[7].z;  m.w += t1.w*w[7].w;  \
    m.x += t2.x*w[8].x;  m.y += t2.x*w[8].y;  m.z += t2.x*w[8].z;  m.w += t2.x*w[8].w;  \
    m.x += t2.y*w[9].x;  m.y += t2.y*w[9].y;  m.z += t2.y*w[9].z;  m.w += t2.y*w[9].w;  \
    m.x += t2.z*w[10].x; m.y += t2.z*w[10].y; m.z += t2.z*w[10].z; m.w += t2.z*w[10].w; \
    m.x += t2.w*w[11].x; m.y += t2.w*w[11].y; m.z += t2.w*w[11].z; m.w += t2.w*w[11].w; \
    m.x += t3.x*w[12].x; m.y += t3.x*w[12].y; m.z += t3.x*w[12].z; m.w += t3.x*w[12].w; \
    m.x += t3.y*w[13].x; m.y += t3.y*w[13].y; m.z += t3.y*w[13].z; m.w += t3.y*w[13].w; \
    m.x += t3.z*w[14].x; m.y += t3.z*w[14].y; m.z += t3.z*w[14].z; m.w += t3.z*w[14].w; \
    m.x += t3.w*w[15].x; m.y += t3.w*w[15].y; m.z += t3.w*w[15].z; m.w += t3.w*w[15].w;

__global__ void __launch_bounds__(256)
aggr_kernel(const float* __restrict__ xin,
            const float* __restrict__ We,
            const float* __restrict__ be,
            const float* __restrict__ eps, int l,
            float* __restrict__ aggr) {
    int lane = threadIdx.x & 31;
    int warp = (blockIdx.x * blockDim.x + threadIdx.x) >> 5;
    int nwarps = (gridDim.x * blockDim.x) >> 5;
    int c0 = lane * 4;

    float4 w[ED];
    #pragma unroll
    for (int k = 0; k < ED; k++)
        w[k] = *(const float4*)(We + k * DD + c0);
    float4 bias = *(const float4*)(be + c0);
    float s = 1.0f + eps[l];

    for (int d = warp; d < NN; d += nwarps) {
        float4 xv = *(const float4*)(xin + (size_t)d * DD + c0);
        float4 acc = make_float4(xv.x * s, xv.y * s, xv.z * s, xv.w * s);
        int beg = g_rowptr[d], end = g_rowptr[d + 1];

        int j = beg;
        for (; j + 1 < end; j += 2) {
            int s0 = g_src[j];
            int s1 = g_src[j + 1];
            const float4* p0 = (const float4*)(g_eattr + (size_t)j * ED);
            float4 a0 = p0[0], a1 = p0[1], a2 = p0[2], a3 = p0[3];
            float4 b0 = p0[4], b1 = p0[5], b2 = p0[6], b3 = p0[7];
            float4 xs0 = *(const float4*)(xin + (size_t)s0 * DD + c0);
            float4 xs1 = *(const float4*)(xin + (size_t)s1 * DD + c0);

            float4 m0 = bias;
            MCHAIN(m0, a0, a1, a2, a3)
            float4 m1 = bias;
            MCHAIN(m1, b0, b1, b2, b3)

            acc.x += fmaxf(m0.x + xs0.x, 0.0f) + fmaxf(m1.x + xs1.x, 0.0f);
            acc.y += fmaxf(m0.y + xs0.y, 0.0f) + fmaxf(m1.y + xs1.y, 0.0f);
            acc.z += fmaxf(m0.z + xs0.z, 0.0f) + fmaxf(m1.z + xs1.z, 0.0f);
            acc.w += fmaxf(m0.w + xs0.w, 0.0f) + fmaxf(m1.w + xs1.w, 0.0f);
        }
        if (j < end) {
            int s0 = g_src[j];
            const float4* p0 = (const float4*)(g_eattr + (size_t)j * ED);
            float4 a0 = p0[0], a1 = p0[1], a2 = p0[2], a3 = p0[3];
            float4 xs0 = *(const float4*)(xin + (size_t)s0 * DD + c0);
            float4 m0 = bias;
            MCHAIN(m0, a0, a1, a2, a3)
            acc.x += fmaxf(m0.x + xs0.x, 0.0f);
            acc.y += fmaxf(m0.y + xs0.y, 0.0f);
            acc.z += fmaxf(m0.z + xs0.z, 0.0f);
            acc.w += fmaxf(m0.w + xs0.w, 0.0f);
        }
        *(float4*)(aggr + (size_t)d * DD + c0) = acc;
    }
}

// ---------------------------------------------------------------------------
// Fused node MLP with tf32 tensor cores (3-way split).
// Persistent, grid=148, 512 threads (16 warps, 4x4 warp grid).
// Each warp: 32 rows x 32 cols = 2 m-tiles x 4 n-tiles of m16n8.
// MMA issue reordered: all j-tiles per split-product (independent chains).
// Fragment layouts (m16n8k8, g=lane>>2, c=lane&3):
//   A: a0=(g,c) a1=(g+8,c) a2=(g,c+4) a3=(g+8,c+4)
//   B: b0=(k=c,n=g) b1=(k=c+4,n=g)
//   C: c0=(g,2c) c1=(g,2c+1) c2=(g+8,2c) c3=(g+8,2c+1)
// ---------------------------------------------------------------------------
#define PITCH 132
#define MLP_TILES ((NN + 127) / 128)     // 391
#define MLP_SMEM_FLOATS (3 * 128 * PITCH + 256)
#define MLP_SMEM_BYTES (MLP_SMEM_FLOATS * 4)

__global__ void __launch_bounds__(512)
mlp_kernel(const float* __restrict__ A,
           const float* __restrict__ W1g,
           const float* __restrict__ b1g,
           const float* __restrict__ W2g,
           const float* __restrict__ b2g,
           float* __restrict__ C) {
    extern __shared__ float sm[];
    float* sA   = sm;                     // 128 x 132 (A tile, then H)
    float* sW1T = sm + 128 * PITCH;       // W1^T : [n][k]
    float* sW2T = sW1T + 128 * PITCH;     // W2^T : [n][k]
    float* sb1  = sW2T + 128 * PITCH;     // 128
    float* sb2  = sb1 + 128;              // 128

    int tid = threadIdx.x;

    // One-time: transposed weight + bias load
    for (int i = tid; i < 128 * 128; i += 512) {
        int k = i >> 7, n = i & 127;      // read coalesced over n
        sW1T[n * PITCH + k] = W1g[i];
        sW2T[n * PITCH + k] = W2g[i];
    }
    if (tid < 128) { sb1[tid] = b1g[tid]; sb2[tid] = b2g[tid]; }

    int lane = tid & 31, wid = tid >> 5;
    int g = lane >> 2, c = lane & 3;      // groupID, tid-in-group
    int wm = wid & 3, wn = wid >> 2;      // warp grid 4 x 4
    int mrow = wm * 32;                   // warp's row base within tile
    int ncol = wn * 32;                   // warp's col base (4 n-tiles)

    for (int tile = blockIdx.x; tile < MLP_TILES; tile += gridDim.x) {
        int row0 = tile * 128;

        __syncthreads();   // previous iteration done reading sA
        for (int i = tid; i < 128 * 32; i += 512) {
            int r = i >> 5, k4 = i & 31;
            int gr = row0 + r;
            float4 v = (gr < NN) ? ((const float4*)(A + (size_t)gr * DD))[k4]
                                 : make_float4(0.f, 0.f, 0.f, 0.f);
            *(float4*)(sA + r * PITCH + k4 * 4) = v;
        }
        __syncthreads();

        float acc[2][4][4];
        #pragma unroll
        for (int mt = 0; mt < 2; mt++)
            #pragma unroll
            for (int j = 0; j < 4; j++)
                #pragma unroll
                for (int q = 0; q < 4; q++) acc[mt][j][q] = 0.0f;

        // ---- GEMM1: A @ W1 ----
        #pragma unroll 1
        for (int s = 0; s < 16; s++) {
            int k0 = s * 8;
            unsigned bhi[4][2], blo[4][2];
            #pragma unroll
            for (int j = 0; j < 4; j++) {
                const float* bp = sW1T + (ncol + 8 * j + g) * PITCH + k0;
                tf32split(bp[c],     bhi[j][0], blo[j][0]);
                tf32split(bp[c + 4], bhi[j][1], blo[j][1]);
            }
            unsigned ahi[2][4], alo[2][4];
            #pragma unroll
            for (int mt = 0; mt < 2; mt++) {
                int r = mrow + mt * 16 + g;
                const float* a0p = sA + r * PITCH + k0;
                const float* a1p = sA + (r + 8) * PITCH + k0;
                tf32split(a0p[c],     ahi[mt][0], alo[mt][0]);
                tf32split(a1p[c],     ahi[mt][1], alo[mt][1]);
                tf32split(a0p[c + 4], ahi[mt][2], alo[mt][2]);
                tf32split(a1p[c + 4], ahi[mt][3], alo[mt][3]);
            }
            // independent-issue order: sweep (mt, j) per product
            #pragma unroll
            for (int mt = 0; mt < 2; mt++)
                #pragma unroll
                for (int j = 0; j < 4; j++) mma_tf32(acc[mt][j], ahi[mt], bhi[j]);
            #pragma unroll
            for (int mt = 0; mt < 2; mt++)
                #pragma unroll
                for (int j = 0; j < 4; j++) mma_tf32(acc[mt][j], ahi[mt], blo[j]);
            #pragma unroll
            for (int mt = 0; mt < 2; mt++)
                #pragma unroll
                for (int j = 0; j < 4; j++) mma_tf32(acc[mt][j], alo[mt], bhi[j]);
        }
        __syncthreads();   // all warps done reading sA

        // ---- epilogue 1: H = gelu_exact(D1 + b1) -> sA ----
        #pragma unroll
        for (int mt = 0; mt < 2; mt++) {
            int r = mrow + mt * 16 + g;
            #pragma unroll
            for (int j = 0; j < 4; j++) {
                int col = ncol + 8 * j + 2 * c;
                float h0 = acc[mt][j][0] + sb1[col];
                float h1 = acc[mt][j][1] + sb1[col + 1];
                float h2 = acc[mt][j][2] + sb1[col];
                float h3 = acc[mt][j][3] + sb1[col + 1];
                h0 = 0.5f * h0 * (1.0f + erff(h0 * 0.70710678118654752f));
                h1 = 0.5f * h1 * (1.0f + erff(h1 * 0.70710678118654752f));
                h2 = 0.5f * h2 * (1.0f + erff(h2 * 0.70710678118654752f));
                h3 = 0.5f * h3 * (1.0f + erff(h3 * 0.70710678118654752f));
                *(float2*)(sA + r * PITCH + col) = make_float2(h0, h1);
                *(float2*)(sA + (r + 8) * PITCH + col) = make_float2(h2, h3);
                acc[mt][j][0] = 0.0f; acc[mt][j][1] = 0.0f;
                acc[mt][j][2] = 0.0f; acc[mt][j][3] = 0.0f;
            }
        }
        __syncthreads();

        // ---- GEMM2: H @ W2 ----
        #pragma unroll 1
        for (int s = 0; s < 16; s++) {
            int k0 = s * 8;
            unsigned bhi[4][2], blo[4][2];
            #pragma unroll
            for (int j = 0; j < 4; j++) {
                const float* bp = sW2T + (ncol + 8 * j + g) * PITCH + k0;
                tf32split(bp[c],     bhi[j][0], blo[j][0]);
                tf32split(bp[c + 4], bhi[j][1], blo[j][1]);
            }
            unsigned ahi[2][4], alo[2][4];
            #pragma unroll
            for (int mt = 0; mt < 2; mt++) {
                int r = mrow + mt * 16 + g;
                const float* a0p = sA + r * PITCH + k0;
                const float* a1p = sA + (r + 8) * PITCH + k0;
                tf32split(a0p[c],     ahi[mt][0], alo[mt][0]);
                tf32split(a1p[c],     ahi[mt][1], alo[mt][1]);
                tf32split(a0p[c + 4], ahi[mt][2], alo[mt][2]);
                tf32split(a1p[c + 4], ahi[mt][3], alo[mt][3]);
            }
            #pragma unroll
            for (int mt = 0; mt < 2; mt++)
                #pragma unroll
                for (int j = 0; j < 4; j++) mma_tf32(acc[mt][j], ahi[mt], bhi[j]);
            #pragma unroll
            for (int mt = 0; mt < 2; mt++)
                #pragma unroll
                for (int j = 0; j < 4; j++) mma_tf32(acc[mt][j], ahi[mt], blo[j]);
            #pragma unroll
            for (int mt = 0; mt < 2; mt++)
                #pragma unroll
                for (int j = 0; j < 4; j++) mma_tf32(acc[mt][j], alo[mt], bhi[j]);
        }

        // ---- epilogue 2: C = D2 + b2 ----
        #pragma unroll
        for (int mt = 0; mt < 2; mt++) {
            int r = mrow + mt * 16 + g;
            int gr0 = row0 + r, gr1 = row0 + r + 8;
            #pragma unroll
            for (int j = 0; j < 4; j++) {
                int col = ncol + 8 * j + 2 * c;
                if (gr0 < NN)
                    *(float2*)(C + (size_t)gr0 * DD + col) =
                        make_float2(acc[mt][j][0] + sb2[col],
                                    acc[mt][j][1] + sb2[col + 1]);
                if (gr1 < NN)
                    *(float2*)(C + (size_t)gr1 * DD + col) =
                        make_float2(acc[mt][j][2] + sb2[col],
                                    acc[mt][j][3] + sb2[col + 1]);
            }
        }
    }
}

// ---------------------------------------------------------------------------
// Launch
// ---------------------------------------------------------------------------
extern "C" void kernel_launch(void* const* d_in, const int* in_sizes, int n_in,
                              void* d_out, int out_size) {
    const float* x         = (const float*)d_in[0];
    const float* edge_attr = (const float*)d_in[1];
    const float* W1        = (const float*)d_in[2];
    const float* b1        = (const float*)d_in[3];
    const float* W2        = (const float*)d_in[4];
    const float* b2        = (const float*)d_in[5];
    const float* We        = (const float*)d_in[6];
    const float* be        = (const float*)d_in[7];
    const float* eps       = (const float*)d_in[8];
    const void*  edge_idx  = d_in[9];
    float* out = (float*)d_out;

    float *bufA, *bufB;
    cudaGetSymbolAddress((void**)&bufA, g_bufA);
    cudaGetSymbolAddress((void**)&bufB, g_bufB);

    cudaFuncSetAttribute(mlp_kernel,
                         cudaFuncAttributeMaxDynamicSharedMemorySize,
                         MLP_SMEM_BYTES);

    // ---- CSR build + attr pre-sort (once per launch) ----
    detect_idx_kernel<<<1, 32>>>((const long long*)edge_idx);
    zero_cnt_kernel<<<(NN + 255) / 256, 256>>>();
    hist_kernel<<<(NE + 255) / 256, 256>>>(edge_idx);
    local_scan_kernel<<<SCAN_NBLK, 1024>>>();
    scan_sums_kernel<<<1, 64>>>();
    add_off_kernel<<<SCAN_NBLK, 1024>>>();
    scatter_fused_kernel<<<(NE + 255) / 256, 256>>>(edge_idx, edge_attr);

    const int aggr_blocks = (NN * 32 + 255) / 256;   // one warp per node

    const float* xin = x;
    for (int l = 0; l < 3; l++) {
        float* aggr = (l == 1) ? bufB : bufA;
        float* xout = (l == 0) ? bufA : ((l == 1) ? bufB : out);

        aggr_kernel<<<aggr_blocks, 256>>>(xin, We + l * ED * DD,
                                          be + l * DD, eps, l, aggr);
        mlp_kernel<<<148, 512, MLP_SMEM_BYTES>>>(
            aggr, W1 + l * DD * DD, b1 + l * DD,
            W2 + l * DD * DD, b2 + l * DD, xout);
        xin = xout;
    }
}